// round 4
// baseline (speedup 1.0000x reference)
#include <cuda_runtime.h>
#include <cooperative_groups.h>
#include <cstdint>

namespace cg = cooperative_groups;

#define T_STEPS   8192
#define HID       1024
#define GATES     4096
#define REC_GRID  128

// ---------------- scratch (static device globals; no allocations) ----------
__device__ float g_gates[(size_t)T_STEPS * GATES];   // 128 MB gate pre-activations
__device__ float g_hbuf[2][HID];                     // double-buffered hidden state

// ---------------- L2-coherent load helper -----------------------------------
__device__ __forceinline__ float ldcg_f(const float* p) {
    float v; asm volatile("ld.global.cg.f32 %0, [%1];" : "=f"(v) : "l"(p)); return v;
}

// ======================= Kernel 1: gates_x GEMM =============================
// C[m,n] = sum_k x[m,k] * W_ih[n,k] + b_ih[n] + b_hh[n]
#define BM 128
#define BN 128
#define BK 8

__global__ __launch_bounds__(256) void gemm_gates_kernel(
    const float* __restrict__ x, const float* __restrict__ Wih,
    const float* __restrict__ b_ih, const float* __restrict__ b_hh)
{
    __shared__ float As[BK][BM + 4];
    __shared__ float Bs[BK][BN + 4];

    const int tid  = threadIdx.x;
    const int arow = tid >> 1;
    const int acol = (tid & 1) << 2;
    const int trow = tid >> 4;
    const int tcol = tid & 15;

    const float* xg = x   + (size_t)(blockIdx.y * BM + arow) * 1024 + acol;
    const float* wg = Wih + (size_t)(blockIdx.x * BN + arow) * 1024 + acol;

    float acc[8][8];
#pragma unroll
    for (int i = 0; i < 8; i++)
#pragma unroll
        for (int j = 0; j < 8; j++) acc[i][j] = 0.f;

    for (int k0 = 0; k0 < 1024; k0 += BK) {
        float4 av = *(const float4*)(xg + k0);
        float4 bv = *(const float4*)(wg + k0);
        As[acol + 0][arow] = av.x; As[acol + 1][arow] = av.y;
        As[acol + 2][arow] = av.z; As[acol + 3][arow] = av.w;
        Bs[acol + 0][arow] = bv.x; Bs[acol + 1][arow] = bv.y;
        Bs[acol + 2][arow] = bv.z; Bs[acol + 3][arow] = bv.w;
        __syncthreads();

#pragma unroll
        for (int k = 0; k < BK; k++) {
            float4 a0 = *(const float4*)&As[k][trow * 8];
            float4 a1 = *(const float4*)&As[k][trow * 8 + 4];
            float4 b0 = *(const float4*)&Bs[k][tcol * 8];
            float4 b1 = *(const float4*)&Bs[k][tcol * 8 + 4];
            float a[8] = {a0.x, a0.y, a0.z, a0.w, a1.x, a1.y, a1.z, a1.w};
            float b[8] = {b0.x, b0.y, b0.z, b0.w, b1.x, b1.y, b1.z, b1.w};
#pragma unroll
            for (int i = 0; i < 8; i++)
#pragma unroll
                for (int j = 0; j < 8; j++)
                    acc[i][j] = fmaf(a[i], b[j], acc[i][j]);
        }
        __syncthreads();
    }

    const int cbase = blockIdx.x * BN + tcol * 8;
    float bias[8];
#pragma unroll
    for (int j = 0; j < 8; j++) bias[j] = b_ih[cbase + j] + b_hh[cbase + j];

#pragma unroll
    for (int i = 0; i < 8; i++) {
        float* crow = g_gates + (size_t)(blockIdx.y * BM + trow * 8 + i) * GATES + cbase;
        float4 o0, o1;
        o0.x = acc[i][0] + bias[0]; o0.y = acc[i][1] + bias[1];
        o0.z = acc[i][2] + bias[2]; o0.w = acc[i][3] + bias[3];
        o1.x = acc[i][4] + bias[4]; o1.y = acc[i][5] + bias[5];
        o1.z = acc[i][6] + bias[6]; o1.w = acc[i][7] + bias[7];
        *(float4*)(crow)     = o0;
        *(float4*)(crow + 4) = o1;
    }
}

// ======================= Kernel 2: cooperative recurrence ===================
// ONE cooperative launch runs all 8192 steps. 128 CTAs x 1024 threads
// (1 CTA/SM; cooperative launch guarantees co-residency or errors out).
// CTA b owns hidden units [8b,8b+8) -> 32 gate rows. W_hh slice lives in
// registers for the whole kernel: warp w holds h-columns [32w,32w+32),
// lane l holds local row l (gate l>>3, unit l&7). grid.sync() separates
// timesteps and provides gpu-scope fencing for the h double-buffer.
__global__ __launch_bounds__(1024, 1) void lstm_rec_coop(
    const float* __restrict__ Whh, const float* __restrict__ h0,
    const float* __restrict__ c0, float* __restrict__ out)
{
    cg::grid_group grid = cg::this_grid();

    __shared__ float h_s[HID];
    __shared__ float part_s[32 * 33];
    __shared__ float red_s[32];
    __shared__ float gx_s[32];
    __shared__ float c_s[8];

    const int tid  = threadIdx.x;
    const int w    = tid >> 5;
    const int l    = tid & 31;
    const int b    = blockIdx.x;
    const int base = b * 8;
    const int R    = (l >> 3) * HID + base + (l & 7);   // this lane's gate row

    // Load W slice into registers (held for the entire sequence).
    float4 Wreg[8];
    {
        const float4* wrow = (const float4*)(Whh + (size_t)R * HID + w * 32);
#pragma unroll
        for (int k = 0; k < 8; k++) Wreg[k] = wrow[k];
    }

    if (tid < 8) c_s[tid] = c0[base + tid];   // cell state stays in SMEM

    for (int t = 0; t < T_STEPS; t++) {
        // ---- phase A: stage h + this step's gates_x slice ----
        const float* src = (t == 0) ? h0 : g_hbuf[t & 1];
        h_s[tid] = ldcg_f(src + tid);
        if (w == 0) gx_s[l] = ldcg_f(&g_gates[(size_t)t * GATES + R]);
        __syncthreads();

        // ---- phase B: 32x32 partial dot (W in regs, h broadcast) ----
        float acc = 0.f;
        const float4* hv = (const float4*)h_s + w * 8;
#pragma unroll
        for (int k = 0; k < 8; k++) {
            float4 h4 = hv[k];
            acc = fmaf(Wreg[k].x, h4.x, acc);
            acc = fmaf(Wreg[k].y, h4.y, acc);
            acc = fmaf(Wreg[k].z, h4.z, acc);
            acc = fmaf(Wreg[k].w, h4.w, acc);
        }
        part_s[w * 33 + l] = acc;
        __syncthreads();

        // ---- phase C: transpose reduce: warp w sums local row w ----
        float v = part_s[l * 33 + w];
#pragma unroll
        for (int s = 16; s > 0; s >>= 1)
            v += __shfl_xor_sync(0xffffffffu, v, s);
        if (l == 0) red_s[w] = v + gx_s[w];
        __syncthreads();

        // ---- phase D: gate math + publish h ----
        if (tid < 8) {
            float xi = red_s[tid];
            float xf = red_s[8 + tid];
            float xg = red_s[16 + tid];
            float xo = red_s[24 + tid];
            float ii = 1.f / (1.f + __expf(-xi));
            float ff = 1.f / (1.f + __expf(-xf));
            float gg = tanhf(xg);
            float oo = 1.f / (1.f + __expf(-xo));
            float c  = fmaf(ff, c_s[tid], ii * gg);
            c_s[tid] = c;
            float h  = oo * tanhf(c);
            out[(size_t)t * HID + base + tid]  = h;
            g_hbuf[(t + 1) & 1][base + tid]    = h;
        }

        // ---- phase E: device-wide barrier (fences the h double-buffer) ----
        grid.sync();
    }
}

// ======================= launch =============================================
extern "C" void kernel_launch(void* const* d_in, const int* in_sizes, int n_in,
                              void* d_out, int out_size)
{
    const float* x    = (const float*)d_in[0];
    const float* Wih  = (const float*)d_in[1];
    const float* Whh  = (const float*)d_in[2];
    const float* b_ih = (const float*)d_in[3];
    const float* b_hh = (const float*)d_in[4];
    const float* h0   = (const float*)d_in[5];
    const float* c0   = (const float*)d_in[6];
    float* out = (float*)d_out;

    dim3 ggrid(GATES / BN, T_STEPS / BM);
    gemm_gates_kernel<<<ggrid, 256>>>(x, Wih, b_ih, b_hh);

    void* args[4] = { (void*)&Whh, (void*)&h0, (void*)&c0, (void*)&out };
    cudaLaunchCooperativeKernel((void*)lstm_rec_coop,
                                dim3(REC_GRID, 1, 1), dim3(1024, 1, 1),
                                args, 0, (cudaStream_t)0);
}